// round 1
// baseline (speedup 1.0000x reference)
#include <cuda_runtime.h>
#include <math.h>

#define NA 4096
#define NB 4096
#define NS 4

// Scratch (device globals — allocation-free per harness rules)
__device__ float g_K [(size_t)NA * NB];   // K[n][m]  = exp(-C[n][m]/eps)
__device__ float g_KT[(size_t)NB * NA];   // KT[m][n] = K[n][m]
__device__ float g_u [NS * NA];           // u = exp(f/eps), s-major [s][n]
__device__ float g_v [NS * NB];           // v = exp(g/eps), s-major [s][m]

// ---------------------------------------------------------------------------
// Kernel 1: K = exp(-C/eps) and its transpose, tiled 32x32.
// ---------------------------------------------------------------------------
__global__ void expT_kernel(const float* __restrict__ C,
                            const float* __restrict__ eps_p) {
    __shared__ float tile[32][33];
    const float scale = -1.44269504088896340736f / eps_p[0];  // exp(-c/eps)=exp2(c*scale)
    const int bx = blockIdx.x * 32, by = blockIdx.y * 32;
    const int tx = threadIdx.x, ty = threadIdx.y;             // blockDim (32, 8)

#pragma unroll
    for (int j = 0; j < 32; j += 8) {
        const int r = by + ty + j;
        const int c = bx + tx;
        const float e = exp2f(C[(size_t)r * NB + c] * scale);
        g_K[(size_t)r * NB + c] = e;
        tile[ty + j][tx] = e;
    }
    __syncthreads();
#pragma unroll
    for (int j = 0; j < 32; j += 8) {
        const int r = bx + ty + j;   // transposed row = original column
        const int c = by + tx;       // transposed col = original row
        g_KT[(size_t)r * NA + c] = tile[tx][ty + j];
    }
}

// ---------------------------------------------------------------------------
// Kernel 2: v = 1  (g0 = 0)
// ---------------------------------------------------------------------------
__global__ void init_v_kernel() {
    const int i = blockIdx.x * blockDim.x + threadIdx.x;
    if (i < NS * NB) g_v[i] = 1.0f;
}

// ---------------------------------------------------------------------------
// Kernel 3: one Sinkhorn half-step.
//   dir=0: u = alpha / (K  v)   (M rows = NA, reduce over NB)
//   dir=1: v = beta  / (KT u)   (M rows = NB, reduce over NA)
// Block: 256 threads (8 warps), 2 rows per warp -> 16 rows/block, 256 blocks.
// x (S x 4096 fp32, s-major) staged in 64KB dynamic smem.
// ---------------------------------------------------------------------------
__global__ void phase_kernel(const int dir, const float* __restrict__ tgt) {
    extern __shared__ float sx[];            // NS * 4096 floats = 64KB
    const float* __restrict__ M = dir ? g_KT : g_K;
    const float* __restrict__ x = dir ? g_u  : g_v;
    float* __restrict__ out     = dir ? g_v  : g_u;

    // Stage x in smem (vectorized)
    {
        const float4* __restrict__ x4 = (const float4*)x;
        float4* sx4 = (float4*)sx;
#pragma unroll
        for (int i = threadIdx.x; i < NS * 1024; i += 256) sx4[i] = x4[i];
    }
    __syncthreads();

    const int warp = threadIdx.x >> 5;
    const int lane = threadIdx.x & 31;
    const int row0 = blockIdx.x * 16 + warp * 2;   // rows row0, row0+1

    const float4* __restrict__ m0 = (const float4*)(M + (size_t)row0 * 4096);
    const float4* __restrict__ m1 = (const float4*)(M + (size_t)(row0 + 1) * 4096);
    const float4* __restrict__ sx4 = (const float4*)sx;

    float a0[NS] = {0.f, 0.f, 0.f, 0.f};
    float a1[NS] = {0.f, 0.f, 0.f, 0.f};

#pragma unroll 4
    for (int it = 0; it < 32; ++it) {
        const int idx = it * 32 + lane;            // float4 index within row
        const float4 k0 = m0[idx];
        const float4 k1 = m1[idx];
#pragma unroll
        for (int s = 0; s < NS; ++s) {
            const float4 xv = sx4[s * 1024 + idx]; // conflict-free LDS.128
            a0[s] = fmaf(k0.x, xv.x, a0[s]);
            a0[s] = fmaf(k0.y, xv.y, a0[s]);
            a0[s] = fmaf(k0.z, xv.z, a0[s]);
            a0[s] = fmaf(k0.w, xv.w, a0[s]);
            a1[s] = fmaf(k1.x, xv.x, a1[s]);
            a1[s] = fmaf(k1.y, xv.y, a1[s]);
            a1[s] = fmaf(k1.z, xv.z, a1[s]);
            a1[s] = fmaf(k1.w, xv.w, a1[s]);
        }
    }

    // Warp butterfly reduction (all lanes end with full sums)
#pragma unroll
    for (int s = 0; s < NS; ++s) {
#pragma unroll
        for (int o = 16; o > 0; o >>= 1) {
            a0[s] += __shfl_xor_sync(0xFFFFFFFFu, a0[s], o);
            a1[s] += __shfl_xor_sync(0xFFFFFFFFu, a1[s], o);
        }
    }

    if (lane == 0) {
#pragma unroll
        for (int s = 0; s < NS; ++s) {
            out[s * 4096 + row0]     = tgt[s * 4096 + row0]     / a0[s];
            out[s * 4096 + row0 + 1] = tgt[s * 4096 + row0 + 1] / a1[s];
        }
    }
}

// ---------------------------------------------------------------------------
// Kernel 4: f = eps*log(u), g = eps*log(v)
// ---------------------------------------------------------------------------
__global__ void finalize_kernel(const float* __restrict__ eps_p,
                                float* __restrict__ out) {
    const int i = blockIdx.x * blockDim.x + threadIdx.x;
    const float eps = eps_p[0];
    if (i < NS * NA) {
        out[i]           = eps * logf(g_u[i]);
        out[i + NS * NA] = eps * logf(g_v[i]);
    }
}

// ---------------------------------------------------------------------------
extern "C" void kernel_launch(void* const* d_in, const int* in_sizes, int n_in,
                              void* d_out, int out_size) {
    const float* alpha = (const float*)d_in[0];   // (4, 4096)
    const float* beta  = (const float*)d_in[1];   // (4, 4096)
    const float* C     = (const float*)d_in[2];   // (4096, 4096)
    const float* eps   = (const float*)d_in[3];   // scalar
    float* out = (float*)d_out;                   // f (4,4096) then g (4,4096)

    cudaFuncSetAttribute(phase_kernel,
                         cudaFuncAttributeMaxDynamicSharedMemorySize, 65536);

    expT_kernel<<<dim3(NB / 32, NA / 32), dim3(32, 8)>>>(C, eps);
    init_v_kernel<<<(NS * NB + 1023) / 1024, 1024>>>();

    for (int it = 0; it < 10; ++it) {
        phase_kernel<<<256, 256, 65536>>>(0, alpha);  // u = alpha/(K v)
        phase_kernel<<<256, 256, 65536>>>(1, beta);   // v = beta /(KT u)
    }

    finalize_kernel<<<(NS * NA + 255) / 256, 256>>>(eps, out);
}

// round 7
// speedup vs baseline: 2.0050x; 2.0050x over previous
#include <cuda_runtime.h>
#include <cuda_fp16.h>
#include <math.h>

#define NA 4096
#define NB 4096
#define NS 4
#define COLT 512              // columns per K tile
#define NTILE (4096 / COLT)   // 8 tiles per row-slab

// Scratch (device globals — allocation-free per harness rules)
__device__ __half g_Kh [(size_t)NA * NB];   // K[n][m]  = exp(-C[n][m]/eps), fp16
__device__ __half g_KTh[(size_t)NB * NA];   // KT[m][n] = K[n][m], fp16
__device__ float  g_u  [NS * NA];           // u = exp(f/eps), s-major
__device__ float  g_v  [NS * NB];           // v = exp(g/eps), s-major

// ---------------------------------------------------------------------------
// cp.async helpers
// ---------------------------------------------------------------------------
__device__ __forceinline__ void cp_async16(unsigned saddr, const void* gptr) {
    asm volatile("cp.async.cg.shared.global [%0], [%1], 16;\n"
                 :: "r"(saddr), "l"(gptr));
}
__device__ __forceinline__ void cp_commit() {
    asm volatile("cp.async.commit_group;\n");
}
template <int N>
__device__ __forceinline__ void cp_wait() {
    asm volatile("cp.async.wait_group %0;\n" :: "n"(N));
}

// ---------------------------------------------------------------------------
// Kernel 1: K = exp(-C/eps) (fp16) and its transpose, tiled 32x32.
// ---------------------------------------------------------------------------
__global__ void expT_kernel(const float* __restrict__ C,
                            const float* __restrict__ eps_p) {
    __shared__ float tile[32][33];
    const float scale = -1.44269504088896340736f / eps_p[0];
    const int bx = blockIdx.x * 32, by = blockIdx.y * 32;
    const int tx = threadIdx.x, ty = threadIdx.y;             // (16, 16)

#pragma unroll
    for (int j = 0; j < 32; j += 16) {
        const int r = by + ty + j;
        const int c = bx + tx * 2;
        const float2 cv = *(const float2*)&C[(size_t)r * NB + c];
        const float e0 = exp2f(cv.x * scale);
        const float e1 = exp2f(cv.y * scale);
        *(__half2*)&g_Kh[(size_t)r * NB + c] = __floats2half2_rn(e0, e1);
        tile[ty + j][tx * 2]     = e0;
        tile[ty + j][tx * 2 + 1] = e1;
    }
    __syncthreads();
#pragma unroll
    for (int j = 0; j < 32; j += 16) {
        const int rr = ty + j;
        const int r  = bx + rr;
        const int c  = by + tx * 2;
        *(__half2*)&g_KTh[(size_t)r * NA + c] =
            __floats2half2_rn(tile[tx * 2][rr], tile[tx * 2 + 1][rr]);
    }
}

__global__ void init_v_kernel() {
    const int i = blockIdx.x * blockDim.x + threadIdx.x;
    if (i < NS * NB) g_v[i] = 1.0f;
}

// ---------------------------------------------------------------------------
// Kernel 3: one Sinkhorn half-step, cp.async double-buffered K pipeline.
//   dir=0: u = alpha / (K  v)    (x = v, scale 1)
//   dir=1: v = beta  / (KT u)    (x = u, scale 2^16 to keep fp16 normal)
// 256 threads / 8 warps, 2 rows per warp -> 16 rows/block, 256 blocks.
// smem: x fp16 (32KB) + 2 K tile buffers (16x512 halves = 16KB each).
// ---------------------------------------------------------------------------
__global__ void phase_kernel(const int dir, const float* __restrict__ tgt) {
    extern __shared__ __half sh[];
    __half* sx = sh;                          // NS*4096 halves
    __half* sk = sh + NS * 4096;              // 2 * 16*COLT halves
    const __half* __restrict__ M = dir ? g_KTh : g_Kh;
    const float*  __restrict__ x = dir ? g_u  : g_v;
    float*        __restrict__ out = dir ? g_v : g_u;
    const float sc = dir ? 65536.0f : 1.0f;

    const int tid = threadIdx.x;
    const int row0b = blockIdx.x * 16;        // first global row of this block
    const __half* __restrict__ Mrow = M + (size_t)row0b * 4096;

    // Stage x (fp32 -> scaled fp16), 2 elements/thread/iter
    {
        const float2* __restrict__ x2 = (const float2*)x;
        __half2* s2 = (__half2*)sx;
#pragma unroll
        for (int i = tid; i < NS * 2048; i += 256) {
            const float2 v = x2[i];
            s2[i] = __floats2half2_rn(v.x * sc, v.y * sc);
        }
    }

    // K tile prefetch: tile t -> buffer (t&1). 1024 16B chunks, 4/thread.
    const unsigned sk_base = (unsigned)__cvta_generic_to_shared(sk);
#define ISSUE_TILE(t)                                                         \
    {                                                                         \
        const __half* gb = Mrow + (t) * COLT;                                 \
        const unsigned sb = sk_base + ((t) & 1) * (16 * COLT * 2);            \
        _Pragma("unroll")                                                     \
        for (int g = tid; g < 1024; g += 256) {                               \
            const int r = g >> 6, c8 = (g & 63) << 3;                         \
            cp_async16(sb + (unsigned)(r * COLT + c8) * 2,                    \
                       gb + (size_t)r * 4096 + c8);                           \
        }                                                                     \
        cp_commit();                                                          \
    }

    ISSUE_TILE(0);

    const int warp = tid >> 5;
    const int lane = tid & 31;
    float a0[NS] = {0.f, 0.f, 0.f, 0.f};
    float a1[NS] = {0.f, 0.f, 0.f, 0.f};

    const uint4* __restrict__ sx4 = (const uint4*)sx;  // 8 halves per uint4

#pragma unroll
    for (int t = 0; t < NTILE; ++t) {
        if (t + 1 < NTILE) { ISSUE_TILE(t + 1); cp_wait<1>(); }
        else               { cp_wait<0>(); }
        __syncthreads();   // tile t visible to all; also covers x staging at t=0

        const uint4* __restrict__ k0p =
            (const uint4*)(sk + ((t & 1) * 16 + warp * 2) * COLT);
        const uint4* __restrict__ k1p = k0p + (COLT / 8);

#pragma unroll
        for (int it = 0; it < COLT / 8 / 32; ++it) {       // 2 iters
            const int idx = it * 32 + lane;
            const uint4 k0 = k0p[idx];
            const uint4 k1 = k1p[idx];
            float2 k0f[4], k1f[4];
#pragma unroll
            for (int q = 0; q < 4; ++q) {
                k0f[q] = __half22float2(((const __half2*)&k0)[q]);
                k1f[q] = __half22float2(((const __half2*)&k1)[q]);
            }
#pragma unroll
            for (int s = 0; s < NS; ++s) {
                const uint4 xv = sx4[s * 512 + t * 64 + idx];
#pragma unroll
                for (int q = 0; q < 4; ++q) {
                    const float2 xf = __half22float2(((const __half2*)&xv)[q]);
                    a0[s] = fmaf(k0f[q].x, xf.x, a0[s]);
                    a0[s] = fmaf(k0f[q].y, xf.y, a0[s]);
                    a1[s] = fmaf(k1f[q].x, xf.x, a1[s]);
                    a1[s] = fmaf(k1f[q].y, xf.y, a1[s]);
                }
            }
        }
        __syncthreads();   // all reads of buffer (t&1) done before reuse
    }

    // Warp butterfly reduction
#pragma unroll
    for (int s = 0; s < NS; ++s) {
#pragma unroll
        for (int o = 16; o > 0; o >>= 1) {
            a0[s] += __shfl_xor_sync(0xFFFFFFFFu, a0[s], o);
            a1[s] += __shfl_xor_sync(0xFFFFFFFFu, a1[s], o);
        }
    }

    if (lane == 0) {
        const int row0 = row0b + warp * 2;
#pragma unroll
        for (int s = 0; s < NS; ++s) {
            out[s * 4096 + row0]     = tgt[s * 4096 + row0]     * sc / a0[s];
            out[s * 4096 + row0 + 1] = tgt[s * 4096 + row0 + 1] * sc / a1[s];
        }
    }
#undef ISSUE_TILE
}

// ---------------------------------------------------------------------------
// Kernel 4: f = eps*log(u), g = eps*log(v)
// ---------------------------------------------------------------------------
__global__ void finalize_kernel(const float* __restrict__ eps_p,
                                float* __restrict__ out) {
    const int i = blockIdx.x * blockDim.x + threadIdx.x;
    const float eps = eps_p[0];
    if (i < NS * NA) {
        out[i]           = eps * logf(g_u[i]);
        out[i + NS * NA] = eps * logf(g_v[i]);
    }
}

// ---------------------------------------------------------------------------
extern "C" void kernel_launch(void* const* d_in, const int* in_sizes, int n_in,
                              void* d_out, int out_size) {
    const float* alpha = (const float*)d_in[0];   // (4, 4096)
    const float* beta  = (const float*)d_in[1];   // (4, 4096)
    const float* C     = (const float*)d_in[2];   // (4096, 4096)
    const float* eps   = (const float*)d_in[3];   // scalar
    float* out = (float*)d_out;                   // f (4,4096) then g (4,4096)

    const int smem = NS * 4096 * 2 + 2 * 16 * COLT * 2;   // 32KB + 32KB = 64KB
    cudaFuncSetAttribute(phase_kernel,
                         cudaFuncAttributeMaxDynamicSharedMemorySize, smem);

    expT_kernel<<<dim3(NB / 32, NA / 32), dim3(16, 16)>>>(C, eps);
    init_v_kernel<<<(NS * NB + 1023) / 1024, 1024>>>();

    for (int it = 0; it < 10; ++it) {
        phase_kernel<<<256, 256, smem>>>(0, alpha);  // u = alpha/(K v)
        phase_kernel<<<256, 256, smem>>>(1, beta);   // v = beta /(KT u)
    }

    finalize_kernel<<<(NS * NA + 255) / 256, 256>>>(eps, out);
}

// round 8
// speedup vs baseline: 2.3015x; 1.1479x over previous
#include <cuda_runtime.h>
#include <cuda_fp16.h>
#include <math.h>

#define NA 4096
#define NB 4096
#define NS 4

// Scratch (device globals — allocation-free per harness rules)
__device__ __half g_Kh [(size_t)NA * NB];   // K[n][m]  = exp(-C[n][m]/eps), fp16
__device__ __half g_KTh[(size_t)NB * NA];   // KT[m][n] = K[n][m], fp16
__device__ float  g_u  [NS * NA];           // u = exp(f/eps), s-major
__device__ float  g_v  [NS * NB];           // v = exp(g/eps), s-major

// ---------------------------------------------------------------------------
// Kernel 1: K = exp(-C/eps) (fp16) and its transpose, tiled 32x32.
// ---------------------------------------------------------------------------
__global__ void expT_kernel(const float* __restrict__ C,
                            const float* __restrict__ eps_p) {
    __shared__ float tile[32][33];
    const float scale = -1.44269504088896340736f / eps_p[0];
    const int bx = blockIdx.x * 32, by = blockIdx.y * 32;
    const int tx = threadIdx.x, ty = threadIdx.y;             // (16, 16)

#pragma unroll
    for (int j = 0; j < 32; j += 16) {
        const int r = by + ty + j;
        const int c = bx + tx * 2;
        const float2 cv = *(const float2*)&C[(size_t)r * NB + c];
        const float e0 = exp2f(cv.x * scale);
        const float e1 = exp2f(cv.y * scale);
        *(__half2*)&g_Kh[(size_t)r * NB + c] = __floats2half2_rn(e0, e1);
        tile[ty + j][tx * 2]     = e0;
        tile[ty + j][tx * 2 + 1] = e1;
    }
    __syncthreads();
#pragma unroll
    for (int j = 0; j < 32; j += 16) {
        const int rr = ty + j;
        const int r  = bx + rr;
        const int c  = by + tx * 2;
        *(__half2*)&g_KTh[(size_t)r * NA + c] =
            __floats2half2_rn(tile[tx * 2][rr], tile[tx * 2 + 1][rr]);
    }
}

__global__ void init_v_kernel() {
    const int i = blockIdx.x * blockDim.x + threadIdx.x;
    if (i < NS * NB) g_v[i] = 1.0f;
}

// ---------------------------------------------------------------------------
// Kernel 3: one Sinkhorn half-step. K streamed by direct LDG.128 (no smem
// round-trip, no per-tile barriers); x staged once in fp16 smem.
//   dir=0: u = alpha / (K  v)    (x = v, scale 1)
//   dir=1: v = beta  / (KT u)    (x = u, scale 2^16 to keep fp16 normal)
// 256 threads / 8 warps, 2 rows per warp -> 16 rows/block, 256 blocks.
// ---------------------------------------------------------------------------
__global__ void __launch_bounds__(256) phase_kernel(const int dir,
                                                    const float* __restrict__ tgt) {
    __shared__ __half sx[NS * 4096];               // 32KB
    const __half* __restrict__ M = dir ? g_KTh : g_Kh;
    const float*  __restrict__ x = dir ? g_u  : g_v;
    float*        __restrict__ out = dir ? g_v : g_u;
    const float sc = dir ? 65536.0f : 1.0f;

    const int tid = threadIdx.x;

    // Stage x (fp32 -> scaled fp16), float4 vectorized: 16 iters/thread
    {
        const float4* __restrict__ x4 = (const float4*)x;
        __half2* s2 = (__half2*)sx;
#pragma unroll
        for (int i = tid; i < NS * 1024; i += 256) {
            const float4 v = x4[i];
            s2[i * 2]     = __floats2half2_rn(v.x * sc, v.y * sc);
            s2[i * 2 + 1] = __floats2half2_rn(v.z * sc, v.w * sc);
        }
    }
    __syncthreads();

    const int warp = tid >> 5;
    const int lane = tid & 31;
    const int row0 = blockIdx.x * 16 + warp * 2;   // rows row0, row0+1

    const uint4* __restrict__ m0  = (const uint4*)(M + (size_t)row0 * 4096);
    const uint4* __restrict__ m1  = (const uint4*)(M + (size_t)(row0 + 1) * 4096);
    const uint4* __restrict__ sx4 = (const uint4*)sx;   // 8 halves per uint4

    float a0[NS] = {0.f, 0.f, 0.f, 0.f};
    float a1[NS] = {0.f, 0.f, 0.f, 0.f};

    // 512 uint4 per row / 32 lanes = 16 col-batches; unroll 4 -> 8 LDG.128
    // front-batched per step (MLP ~1KB/warp in flight).
#pragma unroll
    for (int base = 0; base < 16; base += 4) {
        uint4 k0r[4], k1r[4];
#pragma unroll
        for (int j = 0; j < 4; ++j) {
            const int idx = (base + j) * 32 + lane;
            k0r[j] = m0[idx];
            k1r[j] = m1[idx];
        }
#pragma unroll
        for (int j = 0; j < 4; ++j) {
            const int idx = (base + j) * 32 + lane;
            float2 k0f[4], k1f[4];
#pragma unroll
            for (int q = 0; q < 4; ++q) {
                k0f[q] = __half22float2(((const __half2*)&k0r[j])[q]);
                k1f[q] = __half22float2(((const __half2*)&k1r[j])[q]);
            }
#pragma unroll
            for (int s = 0; s < NS; ++s) {
                const uint4 xv = sx4[s * 512 + idx];   // conflict-free LDS.128
#pragma unroll
                for (int q = 0; q < 4; ++q) {
                    const float2 xf = __half22float2(((const __half2*)&xv)[q]);
                    a0[s] = fmaf(k0f[q].x, xf.x, a0[s]);
                    a0[s] = fmaf(k0f[q].y, xf.y, a0[s]);
                    a1[s] = fmaf(k1f[q].x, xf.x, a1[s]);
                    a1[s] = fmaf(k1f[q].y, xf.y, a1[s]);
                }
            }
        }
    }

    // Warp butterfly reduction
#pragma unroll
    for (int s = 0; s < NS; ++s) {
#pragma unroll
        for (int o = 16; o > 0; o >>= 1) {
            a0[s] += __shfl_xor_sync(0xFFFFFFFFu, a0[s], o);
            a1[s] += __shfl_xor_sync(0xFFFFFFFFu, a1[s], o);
        }
    }

    if (lane == 0) {
#pragma unroll
        for (int s = 0; s < NS; ++s) {
            out[s * 4096 + row0]     = tgt[s * 4096 + row0]     * sc / a0[s];
            out[s * 4096 + row0 + 1] = tgt[s * 4096 + row0 + 1] * sc / a1[s];
        }
    }
}

// ---------------------------------------------------------------------------
// Kernel 4: f = eps*log(u), g = eps*log(v)
// ---------------------------------------------------------------------------
__global__ void finalize_kernel(const float* __restrict__ eps_p,
                                float* __restrict__ out) {
    const int i = blockIdx.x * blockDim.x + threadIdx.x;
    const float eps = eps_p[0];
    if (i < NS * NA) {
        out[i]           = eps * logf(g_u[i]);
        out[i + NS * NA] = eps * logf(g_v[i]);
    }
}

// ---------------------------------------------------------------------------
extern "C" void kernel_launch(void* const* d_in, const int* in_sizes, int n_in,
                              void* d_out, int out_size) {
    const float* alpha = (const float*)d_in[0];   // (4, 4096)
    const float* beta  = (const float*)d_in[1];   // (4, 4096)
    const float* C     = (const float*)d_in[2];   // (4096, 4096)
    const float* eps   = (const float*)d_in[3];   // scalar
    float* out = (float*)d_out;                   // f (4,4096) then g (4,4096)

    expT_kernel<<<dim3(NB / 32, NA / 32), dim3(16, 16)>>>(C, eps);
    init_v_kernel<<<(NS * NB + 1023) / 1024, 1024>>>();

    for (int it = 0; it < 10; ++it) {
        phase_kernel<<<256, 256>>>(0, alpha);  // u = alpha/(K v)
        phase_kernel<<<256, 256>>>(1, beta);   // v = beta /(KT u)
    }

    finalize_kernel<<<(NS * NA + 255) / 256, 256>>>(eps, out);
}

// round 9
// speedup vs baseline: 2.3019x; 1.0001x over previous
#include <cuda_runtime.h>
#include <cuda_fp16.h>
#include <math.h>

#define NA 4096
#define NB 4096
#define NS 4

typedef unsigned long long u64;

// Scratch (device globals — allocation-free per harness rules)
__device__ __half g_Kh [(size_t)NA * NB];   // K[n][m]  = exp(-C[n][m]/eps), fp16
__device__ __half g_KTh[(size_t)NB * NA];   // KT[m][n] = K[n][m], fp16
__device__ float  g_u  [NS * NA];           // u = exp(f/eps), s-major
__device__ float  g_v  [NS * NB];           // v = exp(g/eps), s-major

// ---------------------------------------------------------------------------
// f32x2 packed helpers (sm_103a FFMA2 path — only reachable via PTX)
// ---------------------------------------------------------------------------
__device__ __forceinline__ u64 pack_f32x2(float lo, float hi) {
    u64 r;
    asm("mov.b64 %0, {%1, %2};" : "=l"(r) : "f"(lo), "f"(hi));
    return r;
}
__device__ __forceinline__ void unpack_f32x2(u64 v, float& lo, float& hi) {
    asm("mov.b64 {%0, %1}, %2;" : "=f"(lo), "=f"(hi) : "l"(v));
}
__device__ __forceinline__ void fma_f32x2(u64& acc, u64 a, u64 b) {
    asm("fma.rn.f32x2 %0, %1, %2, %0;" : "+l"(acc) : "l"(a), "l"(b));
}
// half2 -> packed f32x2 (cvt on fma pipe + pack on alu pipe)
__device__ __forceinline__ u64 h2_to_f32x2(__half2 h) {
    const float2 f = __half22float2(h);
    return pack_f32x2(f.x, f.y);
}

// ---------------------------------------------------------------------------
// Kernel 1: K = exp(-C/eps) (fp16) and its transpose, tiled 32x32.
// ---------------------------------------------------------------------------
__global__ void expT_kernel(const float* __restrict__ C,
                            const float* __restrict__ eps_p) {
    __shared__ float tile[32][33];
    const float scale = -1.44269504088896340736f / eps_p[0];
    const int bx = blockIdx.x * 32, by = blockIdx.y * 32;
    const int tx = threadIdx.x, ty = threadIdx.y;             // (16, 16)

#pragma unroll
    for (int j = 0; j < 32; j += 16) {
        const int r = by + ty + j;
        const int c = bx + tx * 2;
        const float2 cv = *(const float2*)&C[(size_t)r * NB + c];
        const float e0 = exp2f(cv.x * scale);
        const float e1 = exp2f(cv.y * scale);
        *(__half2*)&g_Kh[(size_t)r * NB + c] = __floats2half2_rn(e0, e1);
        tile[ty + j][tx * 2]     = e0;
        tile[ty + j][tx * 2 + 1] = e1;
    }
    __syncthreads();
#pragma unroll
    for (int j = 0; j < 32; j += 16) {
        const int rr = ty + j;
        const int r  = bx + rr;
        const int c  = by + tx * 2;
        *(__half2*)&g_KTh[(size_t)r * NA + c] =
            __floats2half2_rn(tile[tx * 2][rr], tile[tx * 2 + 1][rr]);
    }
}

__global__ void init_v_kernel() {
    const int i = blockIdx.x * blockDim.x + threadIdx.x;
    if (i < NS * NB) g_v[i] = 1.0f;
}

// ---------------------------------------------------------------------------
// Kernel 3: one Sinkhorn half-step. K by direct LDG.128; x in fp16 smem.
// Accumulation via packed fma.rn.f32x2 over (even,odd) column pairs.
//   dir=0: u = alpha / (K  v)    (x = v, scale 1)
//   dir=1: v = beta  / (KT u)    (x = u, scale 2^16 to keep fp16 normal)
// 256 threads / 8 warps, 2 rows per warp -> 16 rows/block, 256 blocks.
// ---------------------------------------------------------------------------
__global__ void __launch_bounds__(256) phase_kernel(const int dir,
                                                    const float* __restrict__ tgt) {
    __shared__ __half sx[NS * 4096];               // 32KB
    const __half* __restrict__ M = dir ? g_KTh : g_Kh;
    const float*  __restrict__ x = dir ? g_u  : g_v;
    float*        __restrict__ out = dir ? g_v : g_u;
    const float sc = dir ? 65536.0f : 1.0f;

    const int tid = threadIdx.x;

    // Stage x (fp32 -> scaled fp16), float4 vectorized
    {
        const float4* __restrict__ x4 = (const float4*)x;
        __half2* s2 = (__half2*)sx;
#pragma unroll
        for (int i = tid; i < NS * 1024; i += 256) {
            const float4 v = x4[i];
            s2[i * 2]     = __floats2half2_rn(v.x * sc, v.y * sc);
            s2[i * 2 + 1] = __floats2half2_rn(v.z * sc, v.w * sc);
        }
    }
    __syncthreads();

    const int warp = tid >> 5;
    const int lane = tid & 31;
    const int row0 = blockIdx.x * 16 + warp * 2;   // rows row0, row0+1

    const uint4* __restrict__ m0  = (const uint4*)(M + (size_t)row0 * 4096);
    const uint4* __restrict__ m1  = (const uint4*)(M + (size_t)(row0 + 1) * 4096);
    const uint4* __restrict__ sx4 = (const uint4*)sx;   // 8 halves per uint4

    // acc[r][s]: packed (even-col sum, odd-col sum)
    u64 acc0[NS], acc1[NS];
    const u64 z = pack_f32x2(0.f, 0.f);
#pragma unroll
    for (int s = 0; s < NS; ++s) { acc0[s] = z; acc1[s] = z; }

    // 512 uint4 per row / 32 lanes = 16 col-batches; front-batch 4 -> 8 LDG.128
#pragma unroll
    for (int base = 0; base < 16; base += 4) {
        uint4 k0r[4], k1r[4];
#pragma unroll
        for (int j = 0; j < 4; ++j) {
            const int idx = (base + j) * 32 + lane;
            k0r[j] = m0[idx];
            k1r[j] = m1[idx];
        }
#pragma unroll
        for (int j = 0; j < 4; ++j) {
            const int idx = (base + j) * 32 + lane;
            u64 k0p[4], k1p[4];
#pragma unroll
            for (int q = 0; q < 4; ++q) {
                k0p[q] = h2_to_f32x2(((const __half2*)&k0r[j])[q]);
                k1p[q] = h2_to_f32x2(((const __half2*)&k1r[j])[q]);
            }
#pragma unroll
            for (int s = 0; s < NS; ++s) {
                const uint4 xv = sx4[s * 512 + idx];   // conflict-free LDS.128
#pragma unroll
                for (int q = 0; q < 4; ++q) {
                    const u64 xp = h2_to_f32x2(((const __half2*)&xv)[q]);
                    fma_f32x2(acc0[s], k0p[q], xp);
                    fma_f32x2(acc1[s], k1p[q], xp);
                }
            }
        }
    }

    // Collapse packed pairs, then warp butterfly reduction
    float a0[NS], a1[NS];
#pragma unroll
    for (int s = 0; s < NS; ++s) {
        float lo, hi;
        unpack_f32x2(acc0[s], lo, hi);  a0[s] = lo + hi;
        unpack_f32x2(acc1[s], lo, hi);  a1[s] = lo + hi;
    }
#pragma unroll
    for (int s = 0; s < NS; ++s) {
#pragma unroll
        for (int o = 16; o > 0; o >>= 1) {
            a0[s] += __shfl_xor_sync(0xFFFFFFFFu, a0[s], o);
            a1[s] += __shfl_xor_sync(0xFFFFFFFFu, a1[s], o);
        }
    }

    if (lane == 0) {
#pragma unroll
        for (int s = 0; s < NS; ++s) {
            out[s * 4096 + row0]     = tgt[s * 4096 + row0]     * sc / a0[s];
            out[s * 4096 + row0 + 1] = tgt[s * 4096 + row0 + 1] * sc / a1[s];
        }
    }
}

// ---------------------------------------------------------------------------
// Kernel 4: f = eps*log(u), g = eps*log(v)
// ---------------------------------------------------------------------------
__global__ void finalize_kernel(const float* __restrict__ eps_p,
                                float* __restrict__ out) {
    const int i = blockIdx.x * blockDim.x + threadIdx.x;
    const float eps = eps_p[0];
    if (i < NS * NA) {
        out[i]           = eps * logf(g_u[i]);
        out[i + NS * NA] = eps * logf(g_v[i]);
    }
}

// ---------------------------------------------------------------------------
extern "C" void kernel_launch(void* const* d_in, const int* in_sizes, int n_in,
                              void* d_out, int out_size) {
    const float* alpha = (const float*)d_in[0];   // (4, 4096)
    const float* beta  = (const float*)d_in[1];   // (4, 4096)
    const float* C     = (const float*)d_in[2];   // (4096, 4096)
    const float* eps   = (const float*)d_in[3];   // scalar
    float* out = (float*)d_out;                   // f (4,4096) then g (4,4096)

    expT_kernel<<<dim3(NB / 32, NA / 32), dim3(16, 16)>>>(C, eps);
    init_v_kernel<<<(NS * NB + 1023) / 1024, 1024>>>();

    for (int it = 0; it < 10; ++it) {
        phase_kernel<<<256, 256>>>(0, alpha);  // u = alpha/(K v)
        phase_kernel<<<256, 256>>>(1, beta);   // v = beta /(KT u)
    }

    finalize_kernel<<<(NS * NA + 255) / 256, 256>>>(eps, out);
}